// round 1
// baseline (speedup 1.0000x reference)
#include <cuda_runtime.h>
#include <math.h>

#define BV 64
#define LV 196
#define BT 32
#define NW 24
#define CD 512
#define NKEEP 98
#define NNON 98
#define KEEPED 49
#define HID 102
#define PAIRS (BT*BV)

// ---------------- scratch (device globals; no allocation allowed) -------------
__device__ float g_img_inv[BV*LV];
__device__ float g_self[BV*LV];
__device__ float g_img_glo[BV*CD];
__device__ float g_cap_glo[BT*CD];
__device__ float g_cap_norm[BT*NW*CD];
__device__ float g_score[(size_t)PAIRS*LV];
__device__ int   g_keep[(size_t)PAIRS*NKEEP];
__device__ float g_extra[(size_t)PAIRS*CD];
__device__ float g_wpre[(size_t)BV*LV*KEEPED];

__device__ __forceinline__ float warpSum(float x){
    #pragma unroll
    for (int o=16;o;o>>=1) x += __shfl_xor_sync(0xffffffffu, x, o);
    return x;
}
__device__ __forceinline__ float warpMax(float x){
    #pragma unroll
    for (int o=16;o;o>>=1) x = fmaxf(x, __shfl_xor_sync(0xffffffffu, x, o));
    return x;
}

// ---------------- global token means, l2-normalized (img_glo / cap_glo) -------
__global__ void k_glo(const float* __restrict__ src, int L, int which){
    int b = blockIdx.x;
    __shared__ float s_mean[CD];
    __shared__ float s_red[32];
    for (int c = threadIdx.x; c < CD; c += blockDim.x){
        float s = 0.f;
        for (int l = 0; l < L; l++) s += src[((size_t)b*L + l)*CD + c];
        s_mean[c] = s / (float)L;
    }
    __syncthreads();
    float ss = 0.f;
    for (int c = threadIdx.x; c < CD; c += blockDim.x){ float x = s_mean[c]; ss += x*x; }
    ss = warpSum(ss);
    if ((threadIdx.x & 31) == 0) s_red[threadIdx.x>>5] = ss;
    __syncthreads();
    if (threadIdx.x < 32){
        float v = (threadIdx.x < (blockDim.x>>5)) ? s_red[threadIdx.x] : 0.f;
        v = warpSum(v);
        if (threadIdx.x == 0) s_red[0] = 1.f / fmaxf(sqrtf(v), 1e-12f);
    }
    __syncthreads();
    float inv = s_red[0];
    float* out = which ? g_cap_glo : g_img_glo;
    for (int c = threadIdx.x; c < CD; c += blockDim.x) out[(size_t)b*CD + c] = s_mean[c]*inv;
}

// ---------------- per-img-token inv-norm + self_attn -------------------------
__global__ void k_img_tok(const float* __restrict__ img){
    int idx = blockIdx.x;           // v*LV + l
    int v = idx / LV;
    const float* x   = img + (size_t)idx*CD;
    const float* glo = g_img_glo + (size_t)v*CD;
    float ss = 0.f, dg = 0.f;
    for (int c = threadIdx.x; c < CD; c += 128){ float t = x[c]; ss += t*t; dg += t*glo[c]; }
    ss = warpSum(ss); dg = warpSum(dg);
    __shared__ float r1[4], r2[4];
    if ((threadIdx.x & 31) == 0){ r1[threadIdx.x>>5] = ss; r2[threadIdx.x>>5] = dg; }
    __syncthreads();
    if (threadIdx.x == 0){
        float S = r1[0]+r1[1]+r1[2]+r1[3];
        float D = r2[0]+r2[1]+r2[2]+r2[3];
        float inv = 1.f / fmaxf(sqrtf(S), 1e-12f);
        g_img_inv[idx] = inv;
        g_self[idx]    = D*inv;
    }
}

// ---------------- normalized caption tokens -----------------------------------
__global__ void k_cap_tok(const float* __restrict__ cap){
    int idx = blockIdx.x;           // t*NW + w
    const float* x = cap + (size_t)idx*CD;
    float ss = 0.f;
    for (int c = threadIdx.x; c < CD; c += 128){ float t = x[c]; ss += t*t; }
    ss = warpSum(ss);
    __shared__ float r[4]; __shared__ float s_inv;
    if ((threadIdx.x & 31) == 0) r[threadIdx.x>>5] = ss;
    __syncthreads();
    if (threadIdx.x == 0) s_inv = 1.f / fmaxf(sqrtf(r[0]+r[1]+r[2]+r[3]), 1e-12f);
    __syncthreads();
    float inv = s_inv;
    for (int c = threadIdx.x; c < CD; c += 128) g_cap_norm[(size_t)idx*CD + c] = x[c]*inv;
}

// ---------------- score[t,v,l] = self + cap_glo[t]·img_norm[v,l] --------------
__global__ void k_score(const float* __restrict__ img){
    extern __shared__ float sm[];
    float* s_cap = sm;              // BT*CD
    float* s_emb = sm + BT*CD;      // CD
    int v = blockIdx.x;
    for (int i = threadIdx.x; i < BT*CD; i += 256) s_cap[i] = g_cap_glo[i];
    __syncthreads();
    int warp = threadIdx.x >> 5, lane = threadIdx.x & 31;
    for (int l = 0; l < LV; l++){
        for (int c = threadIdx.x; c < CD; c += 256) s_emb[c] = img[((size_t)v*LV + l)*CD + c];
        __syncthreads();
        float selfv = g_self[v*LV + l], inv = g_img_inv[v*LV + l];
        #pragma unroll
        for (int tt = 0; tt < 4; tt++){
            int t = warp*4 + tt;
            float d = 0.f;
            for (int c = lane; c < CD; c += 32) d += s_cap[t*CD + c] * s_emb[c];
            d = warpSum(d);
            if (lane == 0) g_score[((size_t)t*BV + v)*LV + l] = selfv + d*inv;
        }
        __syncthreads();
    }
}

// ---------------- exact stable descending-rank + extra token ------------------
__global__ void k_rank(const float* __restrict__ img, float* __restrict__ out_mask){
    int pair = blockIdx.x; int v = pair % BV;
    __shared__ float s_sc[LV];
    __shared__ int   s_non[NNON];
    __shared__ float s_nw[NNON];
    __shared__ float s_max, s_sum;
    __shared__ float s_red[8];
    for (int l = threadIdx.x; l < LV; l += 256) s_sc[l] = g_score[(size_t)pair*LV + l];
    __syncthreads();
    for (int l = threadIdx.x; l < LV; l += 256){
        float sl = s_sc[l]; int r = 0;
        #pragma unroll 4
        for (int j = 0; j < LV; j++){
            float sj = s_sc[j];
            r += (int)((sj > sl) || ((sj == sl) && (j < l)));
        }
        out_mask[(size_t)pair*LV + l] = (r < NKEEP) ? 1.f : 0.f;
        if (r < NKEEP) g_keep[(size_t)pair*NKEEP + r] = l;
        else {
            s_non[r - NKEEP] = l;
            if (r == NKEEP) s_max = sl;
        }
    }
    __syncthreads();
    float local = 0.f;
    for (int j = threadIdx.x; j < NNON; j += 256){
        float e = expf(s_sc[s_non[j]] - s_max);
        s_nw[j] = e; local += e;
    }
    local = warpSum(local);
    if ((threadIdx.x & 31) == 0) s_red[threadIdx.x>>5] = local;
    __syncthreads();
    if (threadIdx.x == 0){ float S = 0.f; for (int i = 0; i < 8; i++) S += s_red[i]; s_sum = S; }
    __syncthreads();
    float invs = 1.f / s_sum;
    for (int c = threadIdx.x; c < CD; c += 256){
        float acc = 0.f;
        #pragma unroll 2
        for (int j = 0; j < NNON; j++) acc += s_nw[j] * img[((size_t)v*LV + s_non[j])*CD + c];
        g_extra[(size_t)pair*CD + c] = acc*invs;
    }
}

// ---------------- per-token LN -> W1 -> gelu -> W2 (w_pre) --------------------
#define TOKTILE 28
__global__ void __launch_bounds__(256) k_wpre(
    const float* __restrict__ img, const float* __restrict__ gamma, const float* __restrict__ beta,
    const float* __restrict__ W1, const float* __restrict__ b1,
    const float* __restrict__ W2, const float* __restrict__ b2)
{
    extern __shared__ float sm[];
    float* s_xn = sm;               // TOKTILE*CD
    float* s_h  = sm + TOKTILE*CD;  // TOKTILE*HID
    int v = blockIdx.x, l0 = blockIdx.y*TOKTILE;
    int tid = threadIdx.x, warp = tid>>5, lane = tid & 31;
    for (int tt = warp; tt < TOKTILE; tt += 8){
        const float* x = img + ((size_t)v*LV + l0 + tt)*CD;
        float s = 0.f, s2 = 0.f;
        for (int c = lane; c < CD; c += 32){ float xv = x[c]; s += xv; s2 += xv*xv; }
        s = warpSum(s); s2 = warpSum(s2);
        float mu = s / (float)CD;
        float var = s2 / (float)CD - mu*mu;
        float rstd = rsqrtf(var + 1e-5f);
        for (int c = lane; c < CD; c += 32)
            s_xn[tt*CD + c] = (x[c] - mu)*rstd*gamma[c] + beta[c];
    }
    __syncthreads();
    for (int idx = tid; idx < TOKTILE*HID; idx += 256){
        int tt = idx / HID, hc = idx % HID;
        float acc = b1[hc];
        const float* xr = s_xn + tt*CD;
        #pragma unroll 8
        for (int c = 0; c < CD; c++) acc += xr[c] * W1[c*HID + hc];
        s_h[idx] = 0.5f*acc*(1.f + erff(acc*0.70710678118654752440f));
    }
    __syncthreads();
    for (int idx = tid; idx < TOKTILE*KEEPED; idx += 256){
        int tt = idx / KEEPED, p = idx % KEEPED;
        float acc = b2[p];
        const float* hr = s_h + tt*HID;
        #pragma unroll 6
        for (int hh = 0; hh < HID; hh++) acc += hr[hh] * W2[hh*KEEPED + p];
        g_wpre[((size_t)v*LV + l0 + tt)*KEEPED + p] = acc;
    }
}

// ---------------- big per-(t,v) kernel: softmax-w, aggr, sims/ctx -------------
#define OFF_W    25600            // after sel (50*512)
#define OFF_SCR  30464            // after w (49*99 padded to 4864)
#define OFF_KEEP 43008            // after scr (98*128)
#define OFF_WS   43112            // keep padded to 104 ints
#define OFF_SIM  43944            // 16*52 warp scratch
#define SMEM_BIG_FLOATS 43952

__global__ void __launch_bounds__(512,1) k_big(
    const float* __restrict__ img, const float* __restrict__ scale_ptr, float* __restrict__ out)
{
    extern __shared__ float sm[];
    float* s_sel  = sm;                     // 50*CD
    float* s_w    = sm + OFF_W;             // 49 rows, pitch 99
    float* s_scr  = sm + OFF_SCR;           // max(98*128, 24*512)
    int*   s_keep = (int*)(sm + OFF_KEEP);  // 98
    float* s_ws   = sm + OFF_WS;            // 16*52
    float* s_sim  = sm + OFF_SIM;

    int tid = threadIdx.x, warp = tid>>5, lane = tid & 31;
    int pair = blockIdx.x, t = pair / BV, v = pair % BV;
    if (tid == 0) s_sim[0] = 0.f;
    for (int k = tid; k < NKEEP; k += 512) s_keep[k] = g_keep[(size_t)pair*NKEEP + k];
    __syncthreads();
    float scl = scale_ptr[0];

    // gather w_pre for kept tokens
    for (int idx = tid; idx < NKEEP*KEEPED; idx += 512){
        int k = idx / KEEPED, p = idx % KEEPED;
        s_w[p*99 + k] = g_wpre[((size_t)v*LV + s_keep[k])*KEEPED + p] * scl;
    }
    __syncthreads();

    // softmax over k per p
    for (int p = warp; p < KEEPED; p += 16){
        float m = -1e30f;
        for (int k = lane; k < NKEEP; k += 32) m = fmaxf(m, s_w[p*99 + k]);
        m = warpMax(m);
        float s = 0.f;
        for (int k = lane; k < NKEEP; k += 32){
            float e = expf(s_w[p*99 + k] - m);
            s_w[p*99 + k] = e; s += e;
        }
        s = warpSum(s);
        float inv = 1.f / s;
        for (int k = lane; k < NKEEP; k += 32) s_w[p*99 + k] *= inv;
    }
    __syncthreads();

    // aggr[p][c] = sum_k w[p][k] * tok[k][c], C chunked by 128
    int cg = tid & 31, pg = tid >> 5;
    for (int chunk = 0; chunk < 4; chunk++){
        int c0 = chunk*128;
        for (int idx = tid; idx < NKEEP*128; idx += 512){
            int k = idx >> 7, cc = idx & 127;
            s_scr[idx] = img[((size_t)v*LV + s_keep[k])*CD + c0 + cc];
        }
        __syncthreads();
        float acc[4][4];
        #pragma unroll
        for (int i = 0; i < 4; i++){ acc[i][0]=0.f; acc[i][1]=0.f; acc[i][2]=0.f; acc[i][3]=0.f; }
        int cc = cg*4;
        for (int k = 0; k < NKEEP; k++){
            float4 tv = *(const float4*)&s_scr[k*128 + cc];
            #pragma unroll
            for (int i = 0; i < 4; i++){
                int p = pg + 16*i;
                if (p < KEEPED){
                    float wv = s_w[p*99 + k];
                    acc[i][0] += wv*tv.x; acc[i][1] += wv*tv.y;
                    acc[i][2] += wv*tv.z; acc[i][3] += wv*tv.w;
                }
            }
        }
        #pragma unroll
        for (int i = 0; i < 4; i++){
            int p = pg + 16*i;
            if (p < KEEPED){
                float4 o; o.x=acc[i][0]; o.y=acc[i][1]; o.z=acc[i][2]; o.w=acc[i][3];
                *(float4*)&s_sel[p*CD + c0 + cc] = o;
            }
        }
        __syncthreads();
    }

    // extra token row
    for (int c = tid; c < CD; c += 512) s_sel[49*CD + c] = g_extra[(size_t)pair*CD + c];
    __syncthreads();

    // l2-normalize the 50 rows
    for (int r = warp; r < 50; r += 16){
        float ss = 0.f;
        for (int c = lane; c < CD; c += 32){ float x = s_sel[r*CD + c]; ss += x*x; }
        ss = warpSum(ss);
        float inv = 1.f / fmaxf(sqrtf(ss), 1e-12f);
        for (int c = lane; c < CD; c += 32) s_sel[r*CD + c] *= inv;
    }
    __syncthreads();

    // caption tokens (normalized) into scratch
    for (int i = tid; i < NW*CD; i += 512) s_scr[i] = g_cap_norm[((size_t)t*NW)*CD + i];
    __syncthreads();

    // per-word attention over 50 aggregated tokens
    for (int w = warp; w < NW; w += 16){
        float cap[16];
        #pragma unroll
        for (int j = 0; j < 16; j++) cap[j] = s_scr[w*CD + lane + 32*j];
        float* sw = s_ws + warp*52;
        for (int p = 0; p < 50; p++){
            float d = 0.f;
            #pragma unroll
            for (int j = 0; j < 16; j++) d += cap[j] * s_sel[p*CD + lane + 32*j];
            d = warpSum(d);
            if (lane == 0) sw[p] = d;
        }
        __syncwarp();
        float mm = -1e30f;
        for (int p = lane; p < 50; p += 32) mm = fmaxf(mm, sw[p]);
        mm = warpMax(mm);
        __syncwarp();
        for (int p = lane; p < 50; p += 32) sw[p] = expf(4.0f*(sw[p] - mm));
        __syncwarp();
        // ctx (unnormalized softmax scale cancels under l2norm)
        float cx[16];
        #pragma unroll
        for (int j = 0; j < 16; j++) cx[j] = 0.f;
        for (int p = 0; p < 50; p++){
            float wv = sw[p];
            #pragma unroll
            for (int j = 0; j < 16; j++) cx[j] += wv * s_sel[p*CD + lane + 32*j];
        }
        float num = 0.f, den = 0.f;
        #pragma unroll
        for (int j = 0; j < 16; j++){ num += cap[j]*cx[j]; den += cx[j]*cx[j]; }
        num = warpSum(num); den = warpSum(den);
        if (lane == 0){
            float wsim = num / fmaxf(sqrtf(den), 1e-12f);
            atomicAdd(s_sim, wsim);
        }
        __syncwarp();
    }
    __syncthreads();
    if (tid == 0) out[(size_t)v*BT + t] = s_sim[0] / (float)NW;
}

// -------------------------------- launcher ------------------------------------
extern "C" void kernel_launch(void* const* d_in, const int* in_sizes, int n_in,
                              void* d_out, int out_size)
{
    const float* img   = (const float*)d_in[0];
    const float* cap   = (const float*)d_in[1];
    const float* gamma = (const float*)d_in[3];
    const float* beta  = (const float*)d_in[4];
    const float* W1    = (const float*)d_in[5];
    const float* b1    = (const float*)d_in[6];
    const float* W2    = (const float*)d_in[7];
    const float* b2    = (const float*)d_in[8];
    const float* scale = (const float*)d_in[9];

    float* out_sims = (float*)d_out;               // [BV, BT]
    float* out_mask = (float*)d_out + BV*BT;       // [BT, BV, LV]

    const int SMEM_SCORE = (BT*CD + CD)*4;
    const int SMEM_WPRE  = (TOKTILE*CD + TOKTILE*HID)*4;
    const int SMEM_BIG   = SMEM_BIG_FLOATS*4;

    cudaFuncSetAttribute(k_score, cudaFuncAttributeMaxDynamicSharedMemorySize, SMEM_SCORE);
    cudaFuncSetAttribute(k_wpre,  cudaFuncAttributeMaxDynamicSharedMemorySize, SMEM_WPRE);
    cudaFuncSetAttribute(k_big,   cudaFuncAttributeMaxDynamicSharedMemorySize, SMEM_BIG);

    k_glo<<<BV, 256>>>(img, LV, 0);
    k_glo<<<BT, 256>>>(cap, NW, 1);
    k_img_tok<<<BV*LV, 128>>>(img);
    k_cap_tok<<<BT*NW, 128>>>(cap);
    k_score<<<BV, 256, SMEM_SCORE>>>(img);
    k_rank<<<PAIRS, 256>>>(img, out_mask);
    k_wpre<<<dim3(BV, 7), 256, SMEM_WPRE>>>(img, gamma, beta, W1, b1, W2, b2);
    k_big<<<PAIRS, 512, SMEM_BIG>>>(img, scale, out_sims);
}

// round 2
// speedup vs baseline: 1.1831x; 1.1831x over previous
#include <cuda_runtime.h>
#include <math.h>

#define BV 64
#define LV 196
#define BT 32
#define NW 24
#define CD 512
#define NKEEP 98
#define NNON 98
#define KEEPED 49
#define HID 102
#define PAIRS (BT*BV)

// ---------------- scratch (device globals; no allocation allowed) -------------
__device__ float g_img_inv[BV*LV];
__device__ float g_self[BV*LV];
__device__ float g_img_glo[BV*CD];
__device__ float g_cap_glo[BT*CD];
__device__ float g_cap_norm[BT*NW*CD];
__device__ float g_score[(size_t)PAIRS*LV];
__device__ int   g_keep[(size_t)PAIRS*NKEEP];
__device__ float g_extra[(size_t)PAIRS*CD];
__device__ float g_wpre[(size_t)BV*LV*KEEPED];

typedef unsigned long long ull;

__device__ __forceinline__ float warpSum(float x){
    #pragma unroll
    for (int o=16;o;o>>=1) x += __shfl_xor_sync(0xffffffffu, x, o);
    return x;
}
__device__ __forceinline__ float warpMax(float x){
    #pragma unroll
    for (int o=16;o;o>>=1) x = fmaxf(x, __shfl_xor_sync(0xffffffffu, x, o));
    return x;
}

// packed f32x2 helpers (sm_103a FFMA2 path — PTX-only)
__device__ __forceinline__ ull pk2(float a, float b){
    ull r; asm("mov.b64 %0, {%1, %2};" : "=l"(r) : "f"(a), "f"(b)); return r;
}
__device__ __forceinline__ float2 upk2(ull v){
    float2 r; asm("mov.b64 {%0, %1}, %2;" : "=f"(r.x), "=f"(r.y) : "l"(v)); return r;
}
__device__ __forceinline__ void fma2(ull &d, ull a, ull b){
    asm("fma.rn.f32x2 %0, %1, %2, %0;" : "+l"(d) : "l"(a), "l"(b));
}

// ---------------- global token means, l2-normalized (img_glo / cap_glo) -------
__global__ void k_glo(const float* __restrict__ src, int L, int which){
    int b = blockIdx.x;
    __shared__ float s_mean[CD];
    __shared__ float s_red[32];
    for (int c = threadIdx.x; c < CD; c += blockDim.x){
        float s = 0.f;
        for (int l = 0; l < L; l++) s += src[((size_t)b*L + l)*CD + c];
        s_mean[c] = s / (float)L;
    }
    __syncthreads();
    float ss = 0.f;
    for (int c = threadIdx.x; c < CD; c += blockDim.x){ float x = s_mean[c]; ss += x*x; }
    ss = warpSum(ss);
    if ((threadIdx.x & 31) == 0) s_red[threadIdx.x>>5] = ss;
    __syncthreads();
    if (threadIdx.x < 32){
        float v = (threadIdx.x < (blockDim.x>>5)) ? s_red[threadIdx.x] : 0.f;
        v = warpSum(v);
        if (threadIdx.x == 0) s_red[0] = 1.f / fmaxf(sqrtf(v), 1e-12f);
    }
    __syncthreads();
    float inv = s_red[0];
    float* out = which ? g_cap_glo : g_img_glo;
    for (int c = threadIdx.x; c < CD; c += blockDim.x) out[(size_t)b*CD + c] = s_mean[c]*inv;
}

// ---------------- per-img-token inv-norm + self_attn -------------------------
__global__ void k_img_tok(const float* __restrict__ img){
    int idx = blockIdx.x;           // v*LV + l
    int v = idx / LV;
    const float* x   = img + (size_t)idx*CD;
    const float* glo = g_img_glo + (size_t)v*CD;
    float ss = 0.f, dg = 0.f;
    for (int c = threadIdx.x; c < CD; c += 128){ float t = x[c]; ss += t*t; dg += t*glo[c]; }
    ss = warpSum(ss); dg = warpSum(dg);
    __shared__ float r1[4], r2[4];
    if ((threadIdx.x & 31) == 0){ r1[threadIdx.x>>5] = ss; r2[threadIdx.x>>5] = dg; }
    __syncthreads();
    if (threadIdx.x == 0){
        float S = r1[0]+r1[1]+r1[2]+r1[3];
        float D = r2[0]+r2[1]+r2[2]+r2[3];
        float inv = 1.f / fmaxf(sqrtf(S), 1e-12f);
        g_img_inv[idx] = inv;
        g_self[idx]    = D*inv;
    }
}

// ---------------- normalized caption tokens -----------------------------------
__global__ void k_cap_tok(const float* __restrict__ cap){
    int idx = blockIdx.x;           // t*NW + w
    const float* x = cap + (size_t)idx*CD;
    float ss = 0.f;
    for (int c = threadIdx.x; c < CD; c += 128){ float t = x[c]; ss += t*t; }
    ss = warpSum(ss);
    __shared__ float r[4]; __shared__ float s_inv;
    if ((threadIdx.x & 31) == 0) r[threadIdx.x>>5] = ss;
    __syncthreads();
    if (threadIdx.x == 0) s_inv = 1.f / fmaxf(sqrtf(r[0]+r[1]+r[2]+r[3]), 1e-12f);
    __syncthreads();
    float inv = s_inv;
    for (int c = threadIdx.x; c < CD; c += 128) g_cap_norm[(size_t)idx*CD + c] = x[c]*inv;
}

// ---------------- score[t,v,l] = self + cap_glo[t]·img_norm[v,l] --------------
__global__ void k_score(const float* __restrict__ img){
    extern __shared__ float sm[];
    float* s_cap = sm;              // BT*CD
    float* s_emb = sm + BT*CD;      // CD
    int v = blockIdx.x;
    for (int i = threadIdx.x; i < BT*CD; i += 256) s_cap[i] = g_cap_glo[i];
    __syncthreads();
    int warp = threadIdx.x >> 5, lane = threadIdx.x & 31;
    const ull* cap2 = (const ull*)s_cap;
    const ull* emb2 = (const ull*)s_emb;
    for (int l = 0; l < LV; l++){
        for (int c = threadIdx.x; c < CD; c += 256) s_emb[c] = img[((size_t)v*LV + l)*CD + c];
        __syncthreads();
        float selfv = g_self[v*LV + l], inv = g_img_inv[v*LV + l];
        #pragma unroll
        for (int tt = 0; tt < 4; tt++){
            int t = warp*4 + tt;
            ull d2 = 0ull;
            #pragma unroll
            for (int j = 0; j < 8; j++) fma2(d2, cap2[t*256 + lane + 32*j], emb2[lane + 32*j]);
            float2 df = upk2(d2);
            float d = warpSum(df.x + df.y);
            if (lane == 0) g_score[((size_t)t*BV + v)*LV + l] = selfv + d*inv;
        }
        __syncthreads();
    }
}

// ---------------- exact stable descending-rank + extra token ------------------
__global__ void k_rank(const float* __restrict__ img, float* __restrict__ out_mask){
    int pair = blockIdx.x; int v = pair % BV;
    __shared__ float s_sc[LV];
    __shared__ int   s_non[NNON];
    __shared__ float s_nw[NNON];
    __shared__ float s_max, s_sum;
    __shared__ float s_red[8];
    for (int l = threadIdx.x; l < LV; l += 256) s_sc[l] = g_score[(size_t)pair*LV + l];
    __syncthreads();
    for (int l = threadIdx.x; l < LV; l += 256){
        float sl = s_sc[l]; int r = 0;
        #pragma unroll 4
        for (int j = 0; j < LV; j++){
            float sj = s_sc[j];
            r += (int)((sj > sl) || ((sj == sl) && (j < l)));
        }
        out_mask[(size_t)pair*LV + l] = (r < NKEEP) ? 1.f : 0.f;
        if (r < NKEEP) g_keep[(size_t)pair*NKEEP + r] = l;
        else {
            s_non[r - NKEEP] = l;
            if (r == NKEEP) s_max = sl;
        }
    }
    __syncthreads();
    float local = 0.f;
    for (int j = threadIdx.x; j < NNON; j += 256){
        float e = expf(s_sc[s_non[j]] - s_max);
        s_nw[j] = e; local += e;
    }
    local = warpSum(local);
    if ((threadIdx.x & 31) == 0) s_red[threadIdx.x>>5] = local;
    __syncthreads();
    if (threadIdx.x == 0){ float S = 0.f; for (int i = 0; i < 8; i++) S += s_red[i]; s_sum = S; }
    __syncthreads();
    float invs = 1.f / s_sum;
    for (int c = threadIdx.x; c < CD; c += 256){
        float acc = 0.f;
        #pragma unroll 2
        for (int j = 0; j < NNON; j++) acc += s_nw[j] * img[((size_t)v*LV + s_non[j])*CD + c];
        g_extra[(size_t)pair*CD + c] = acc*invs;
    }
}

// ---------------- per-token LN -> W1 -> gelu -> W2 (w_pre) --------------------
// xn stored transposed [c][token] (pitch 30) so the W1 GEMM streams W1 once per
// block (coalesced LDG, register-resident column) with f32x2 token-pair accums.
#define TOKTILE 28
#define XN_P 30
__global__ void __launch_bounds__(256) k_wpre(
    const float* __restrict__ img, const float* __restrict__ gamma, const float* __restrict__ beta,
    const float* __restrict__ W1, const float* __restrict__ b1,
    const float* __restrict__ W2, const float* __restrict__ b2)
{
    extern __shared__ float sm[];
    float* s_xnT = sm;                 // CD*XN_P  (15360 floats)
    float* s_h   = sm + CD*XN_P;       // TOKTILE*HID
    int v = blockIdx.x, l0 = blockIdx.y*TOKTILE;
    int tid = threadIdx.x, warp = tid>>5, lane = tid & 31;

    // LayerNorm, write transposed
    for (int tt = warp; tt < TOKTILE; tt += 8){
        const float* x = img + ((size_t)v*LV + l0 + tt)*CD;
        float s = 0.f, s2 = 0.f;
        for (int c = lane; c < CD; c += 32){ float xv = x[c]; s += xv; s2 += xv*xv; }
        s = warpSum(s); s2 = warpSum(s2);
        float mu = s / (float)CD;
        float var = s2 / (float)CD - mu*mu;
        float rstd = rsqrtf(var + 1e-5f);
        for (int c = lane; c < CD; c += 32)
            s_xnT[c*XN_P + tt] = (x[c] - mu)*rstd*gamma[c] + beta[c];
    }
    __syncthreads();

    // W1 GEMM: thread = (token-group g, hidden-channel hc); 7 f32x2 accumulators
    {
        int hc = tid & 127;
        int g  = tid >> 7;               // 0 or 1 -> tokens g*14 .. g*14+13
        bool act = hc < HID;
        ull acc2[7] = {0ull,0ull,0ull,0ull,0ull,0ull,0ull};
        int tbase = g*14;
        for (int c = 0; c < CD; c++){
            float w1 = act ? W1[c*HID + hc] : 0.f;
            ull w2v = pk2(w1, w1);
            const ull* xr = (const ull*)&s_xnT[c*XN_P + tbase];
            #pragma unroll
            for (int j = 0; j < 7; j++) fma2(acc2[j], w2v, xr[j]);
        }
        if (act){
            float bb = b1[hc];
            #pragma unroll
            for (int j = 0; j < 7; j++){
                float2 hv = upk2(acc2[j]);
                float a0 = hv.x + bb, a1 = hv.y + bb;
                s_h[(tbase + 2*j    )*HID + hc] = 0.5f*a0*(1.f + erff(a0*0.70710678118654752440f));
                s_h[(tbase + 2*j + 1)*HID + hc] = 0.5f*a1*(1.f + erff(a1*0.70710678118654752440f));
            }
        }
    }
    __syncthreads();

    // W2 (small): per (token, p)
    for (int idx = tid; idx < TOKTILE*KEEPED; idx += 256){
        int tt = idx / KEEPED, p = idx % KEEPED;
        float acc = b2[p];
        const float* hr = s_h + tt*HID;
        #pragma unroll 6
        for (int hh = 0; hh < HID; hh++) acc += hr[hh] * W2[hh*KEEPED + p];
        g_wpre[((size_t)v*LV + l0 + tt)*KEEPED + p] = acc;
    }
}

// ---------------- big per-(t,v) kernel: softmax-w, aggr, sims/ctx -------------
#define OFF_W    25600            // after sel (50*512)
#define OFF_SCR  30464            // after w (49*99 padded to 4864)
#define OFF_KEEP 43008            // after scr (98*128)
#define OFF_WS   43112            // keep padded to 104 ints
#define OFF_SIM  43944            // 16*52 warp scratch
#define SMEM_BIG_FLOATS 43952

__global__ void __launch_bounds__(512,1) k_big(
    const float* __restrict__ img, const float* __restrict__ scale_ptr, float* __restrict__ out)
{
    extern __shared__ float sm[];
    float* s_sel  = sm;                     // 50*CD
    float* s_w    = sm + OFF_W;             // 49 rows, pitch 99
    float* s_scr  = sm + OFF_SCR;           // max(98*128, 24*512)
    int*   s_keep = (int*)(sm + OFF_KEEP);  // 98
    float* s_ws   = sm + OFF_WS;            // 16*52
    float* s_sim  = sm + OFF_SIM;

    int tid = threadIdx.x, warp = tid>>5, lane = tid & 31;
    int pair = blockIdx.x, t = pair / BV, v = pair % BV;
    if (tid == 0) s_sim[0] = 0.f;
    for (int k = tid; k < NKEEP; k += 512) s_keep[k] = g_keep[(size_t)pair*NKEEP + k];
    __syncthreads();
    float scl = scale_ptr[0];

    // gather w_pre for kept tokens
    for (int idx = tid; idx < NKEEP*KEEPED; idx += 512){
        int k = idx / KEEPED, p = idx % KEEPED;
        s_w[p*99 + k] = g_wpre[((size_t)v*LV + s_keep[k])*KEEPED + p] * scl;
    }
    __syncthreads();

    // softmax over k per p
    for (int p = warp; p < KEEPED; p += 16){
        float m = -1e30f;
        for (int k = lane; k < NKEEP; k += 32) m = fmaxf(m, s_w[p*99 + k]);
        m = warpMax(m);
        float s = 0.f;
        for (int k = lane; k < NKEEP; k += 32){
            float e = expf(s_w[p*99 + k] - m);
            s_w[p*99 + k] = e; s += e;
        }
        s = warpSum(s);
        float inv = 1.f / s;
        for (int k = lane; k < NKEEP; k += 32) s_w[p*99 + k] *= inv;
    }
    __syncthreads();

    // aggr[p][c] = sum_k w[p][k] * tok[k][c], C chunked by 128, f32x2 math
    int cg = tid & 31, pg = tid >> 5;
    for (int chunk = 0; chunk < 4; chunk++){
        int c0 = chunk*128;
        for (int idx = tid; idx < NKEEP*128; idx += 512){
            int k = idx >> 7, cc = idx & 127;
            s_scr[idx] = img[((size_t)v*LV + s_keep[k])*CD + c0 + cc];
        }
        __syncthreads();
        ull acc[4][2];
        #pragma unroll
        for (int i = 0; i < 4; i++){ acc[i][0]=0ull; acc[i][1]=0ull; }
        int cc = cg*4;
        for (int k = 0; k < NKEEP; k++){
            ulonglong2 tv = *(const ulonglong2*)&s_scr[k*128 + cc];
            #pragma unroll
            for (int i = 0; i < 4; i++){
                int p = pg + 16*i;
                if (p < KEEPED){
                    float wv = s_w[p*99 + k];
                    ull w2v = pk2(wv, wv);
                    fma2(acc[i][0], w2v, tv.x);
                    fma2(acc[i][1], w2v, tv.y);
                }
            }
        }
        #pragma unroll
        for (int i = 0; i < 4; i++){
            int p = pg + 16*i;
            if (p < KEEPED){
                *(ulonglong2*)&s_sel[p*CD + c0 + cc] = make_ulonglong2(acc[i][0], acc[i][1]);
            }
        }
        __syncthreads();
    }

    // extra token row
    for (int c = tid; c < CD; c += 512) s_sel[49*CD + c] = g_extra[(size_t)pair*CD + c];
    __syncthreads();

    // l2-normalize the 50 rows
    for (int r = warp; r < 50; r += 16){
        float ss = 0.f;
        for (int c = lane; c < CD; c += 32){ float x = s_sel[r*CD + c]; ss += x*x; }
        ss = warpSum(ss);
        float inv = 1.f / fmaxf(sqrtf(ss), 1e-12f);
        for (int c = lane; c < CD; c += 32) s_sel[r*CD + c] *= inv;
    }
    __syncthreads();

    // caption tokens (normalized) into scratch
    for (int i = tid; i < NW*CD; i += 512) s_scr[i] = g_cap_norm[((size_t)t*NW)*CD + i];
    __syncthreads();

    // per-word attention over 50 aggregated tokens (f32x2 dots + ctx)
    for (int w = warp; w < NW; w += 16){
        ull cap2[8];
        #pragma unroll
        for (int j = 0; j < 8; j++) cap2[j] = *(const ull*)&s_scr[w*CD + lane*2 + 64*j];
        float* sw = s_ws + warp*52;
        for (int p = 0; p < 50; p++){
            ull d2 = 0ull;
            #pragma unroll
            for (int j = 0; j < 8; j++) fma2(d2, cap2[j], *(const ull*)&s_sel[p*CD + lane*2 + 64*j]);
            float2 df = upk2(d2);
            float d = warpSum(df.x + df.y);
            if (lane == 0) sw[p] = d;
        }
        __syncwarp();
        float mm = -1e30f;
        for (int p = lane; p < 50; p += 32) mm = fmaxf(mm, sw[p]);
        mm = warpMax(mm);
        __syncwarp();
        for (int p = lane; p < 50; p += 32) sw[p] = expf(4.0f*(sw[p] - mm));
        __syncwarp();
        // ctx (unnormalized softmax scale cancels under l2norm)
        ull cx2[8];
        #pragma unroll
        for (int j = 0; j < 8; j++) cx2[j] = 0ull;
        for (int p = 0; p < 50; p++){
            float wv = sw[p];
            ull w2v = pk2(wv, wv);
            #pragma unroll
            for (int j = 0; j < 8; j++) fma2(cx2[j], w2v, *(const ull*)&s_sel[p*CD + lane*2 + 64*j]);
        }
        float num = 0.f, den = 0.f;
        #pragma unroll
        for (int j = 0; j < 8; j++){
            float2 c2 = upk2(cx2[j]); float2 ca = upk2(cap2[j]);
            num += ca.x*c2.x + ca.y*c2.y;
            den += c2.x*c2.x + c2.y*c2.y;
        }
        num = warpSum(num); den = warpSum(den);
        if (lane == 0){
            float wsim = num / fmaxf(sqrtf(den), 1e-12f);
            atomicAdd(s_sim, wsim);
        }
        __syncwarp();
    }
    __syncthreads();
    if (tid == 0) out[(size_t)v*BT + t] = s_sim[0] / (float)NW;
}

// -------------------------------- launcher ------------------------------------
extern "C" void kernel_launch(void* const* d_in, const int* in_sizes, int n_in,
                              void* d_out, int out_size)
{
    const float* img   = (const float*)d_in[0];
    const float* cap   = (const float*)d_in[1];
    const float* gamma = (const float*)d_in[3];
    const float* beta  = (const float*)d_in[4];
    const float* W1    = (const float*)d_in[5];
    const float* b1    = (const float*)d_in[6];
    const float* W2    = (const float*)d_in[7];
    const float* b2    = (const float*)d_in[8];
    const float* scale = (const float*)d_in[9];

    float* out_sims = (float*)d_out;               // [BV, BT]
    float* out_mask = (float*)d_out + BV*BT;       // [BT, BV, LV]

    const int SMEM_SCORE = (BT*CD + CD)*4;
    const int SMEM_WPRE  = (CD*XN_P + TOKTILE*HID)*4;
    const int SMEM_BIG   = SMEM_BIG_FLOATS*4;

    cudaFuncSetAttribute(k_score, cudaFuncAttributeMaxDynamicSharedMemorySize, SMEM_SCORE);
    cudaFuncSetAttribute(k_wpre,  cudaFuncAttributeMaxDynamicSharedMemorySize, SMEM_WPRE);
    cudaFuncSetAttribute(k_big,   cudaFuncAttributeMaxDynamicSharedMemorySize, SMEM_BIG);

    k_glo<<<BV, 256>>>(img, LV, 0);
    k_glo<<<BT, 256>>>(cap, NW, 1);
    k_img_tok<<<BV*LV, 128>>>(img);
    k_cap_tok<<<BT*NW, 128>>>(cap);
    k_score<<<BV, 256, SMEM_SCORE>>>(img);
    k_rank<<<PAIRS, 256>>>(img, out_mask);
    k_wpre<<<dim3(BV, 7), 256, SMEM_WPRE>>>(img, gamma, beta, W1, b1, W2, b2);
    k_big<<<PAIRS, 512, SMEM_BIG>>>(img, scale, out_sims);
}

// round 3
// speedup vs baseline: 1.5647x; 1.3225x over previous
#include <cuda_runtime.h>
#include <math.h>

#define BV 64
#define LV 196
#define BT 32
#define NW 24
#define CD 512
#define NKEEP 98
#define NNON 98
#define KEEPED 49
#define HID 102
#define PAIRS (BT*BV)

// ---------------- scratch (device globals; no allocation allowed) -------------
__device__ float g_img_inv[BV*LV];
__device__ float g_self[BV*LV];
__device__ float g_img_glo[BV*CD];
__device__ float g_cap_glo[BT*CD];
__device__ float g_cap_norm[BT*NW*CD];
__device__ float g_score[(size_t)PAIRS*LV];
__device__ int   g_keep[(size_t)PAIRS*NKEEP];
__device__ float g_extra[(size_t)PAIRS*CD];
__device__ float g_wpre[(size_t)BV*LV*KEEPED];

typedef unsigned long long ull;

__device__ __forceinline__ float warpSum(float x){
    #pragma unroll
    for (int o=16;o;o>>=1) x += __shfl_xor_sync(0xffffffffu, x, o);
    return x;
}
__device__ __forceinline__ float warpMax(float x){
    #pragma unroll
    for (int o=16;o;o>>=1) x = fmaxf(x, __shfl_xor_sync(0xffffffffu, x, o));
    return x;
}

// packed f32x2 helpers (sm_103a FFMA2 path — PTX-only)
__device__ __forceinline__ ull pk2(float a, float b){
    ull r; asm("mov.b64 %0, {%1, %2};" : "=l"(r) : "f"(a), "f"(b)); return r;
}
__device__ __forceinline__ float2 upk2(ull v){
    float2 r; asm("mov.b64 {%0, %1}, %2;" : "=f"(r.x), "=f"(r.y) : "l"(v)); return r;
}
__device__ __forceinline__ void fma2(ull &d, ull a, ull b){
    asm("fma.rn.f32x2 %0, %1, %2, %0;" : "+l"(d) : "l"(a), "l"(b));
}

// ---------------- global token means, l2-normalized (img_glo / cap_glo) -------
__global__ void k_glo(const float* __restrict__ src, int L, int which){
    int b = blockIdx.x;
    __shared__ float s_mean[CD];
    __shared__ float s_red[32];
    for (int c = threadIdx.x; c < CD; c += blockDim.x){
        float s = 0.f;
        for (int l = 0; l < L; l++) s += src[((size_t)b*L + l)*CD + c];
        s_mean[c] = s / (float)L;
    }
    __syncthreads();
    float ss = 0.f;
    for (int c = threadIdx.x; c < CD; c += blockDim.x){ float x = s_mean[c]; ss += x*x; }
    ss = warpSum(ss);
    if ((threadIdx.x & 31) == 0) s_red[threadIdx.x>>5] = ss;
    __syncthreads();
    if (threadIdx.x < 32){
        float v = (threadIdx.x < (blockDim.x>>5)) ? s_red[threadIdx.x] : 0.f;
        v = warpSum(v);
        if (threadIdx.x == 0) s_red[0] = 1.f / fmaxf(sqrtf(v), 1e-12f);
    }
    __syncthreads();
    float inv = s_red[0];
    float* out = which ? g_cap_glo : g_img_glo;
    for (int c = threadIdx.x; c < CD; c += blockDim.x) out[(size_t)b*CD + c] = s_mean[c]*inv;
}

// ---------------- per-img-token inv-norm + self_attn -------------------------
__global__ void k_img_tok(const float* __restrict__ img){
    int idx = blockIdx.x;           // v*LV + l
    int v = idx / LV;
    const float* x   = img + (size_t)idx*CD;
    const float* glo = g_img_glo + (size_t)v*CD;
    float ss = 0.f, dg = 0.f;
    for (int c = threadIdx.x; c < CD; c += 128){ float t = x[c]; ss += t*t; dg += t*glo[c]; }
    ss = warpSum(ss); dg = warpSum(dg);
    __shared__ float r1[4], r2[4];
    if ((threadIdx.x & 31) == 0){ r1[threadIdx.x>>5] = ss; r2[threadIdx.x>>5] = dg; }
    __syncthreads();
    if (threadIdx.x == 0){
        float S = r1[0]+r1[1]+r1[2]+r1[3];
        float D = r2[0]+r2[1]+r2[2]+r2[3];
        float inv = 1.f / fmaxf(sqrtf(S), 1e-12f);
        g_img_inv[idx] = inv;
        g_self[idx]    = D*inv;
    }
}

// ---------------- normalized caption tokens -----------------------------------
__global__ void k_cap_tok(const float* __restrict__ cap){
    int idx = blockIdx.x;           // t*NW + w
    const float* x = cap + (size_t)idx*CD;
    float ss = 0.f;
    for (int c = threadIdx.x; c < CD; c += 128){ float t = x[c]; ss += t*t; }
    ss = warpSum(ss);
    __shared__ float r[4]; __shared__ float s_inv;
    if ((threadIdx.x & 31) == 0) r[threadIdx.x>>5] = ss;
    __syncthreads();
    if (threadIdx.x == 0) s_inv = 1.f / fmaxf(sqrtf(r[0]+r[1]+r[2]+r[3]), 1e-12f);
    __syncthreads();
    float inv = s_inv;
    for (int c = threadIdx.x; c < CD; c += 128) g_cap_norm[(size_t)idx*CD + c] = x[c]*inv;
}

// ---------------- score via 4x4 register-tiled dots ---------------------------
// grid (BV, 7): each block handles 28 l's. smem: cap 32x512, img 28x512.
#define SC_LT 28
__global__ void __launch_bounds__(256) k_score(const float* __restrict__ img){
    extern __shared__ float sm[];
    float* s_cap = sm;                   // 32*512
    float* s_img = sm + BT*CD;           // 28*512
    float* s_self = sm + BT*CD + SC_LT*CD;   // 28
    float* s_inv  = s_self + SC_LT;          // 28
    int v = blockIdx.x, l0 = blockIdx.y*SC_LT;
    int tid = threadIdx.x, warp = tid>>5, lane = tid & 31;
    for (int i = tid; i < BT*CD; i += 256) s_cap[i] = g_cap_glo[i];
    for (int i = tid; i < SC_LT*CD; i += 256) s_img[i] = img[((size_t)v*LV + l0)*CD + i];
    if (tid < SC_LT){ s_self[tid] = g_self[v*LV + l0 + tid]; s_inv[tid] = g_img_inv[v*LV + l0 + tid]; }
    __syncthreads();
    // tiles: 8 t-tiles x 7 l-tiles = 56, 8 warps
    for (int tile = warp; tile < 56; tile += 8){
        int tt0 = (tile / 7)*4, ll0 = (tile % 7)*4;
        ull acc[16];
        #pragma unroll
        for (int q = 0; q < 16; q++) acc[q] = 0ull;
        #pragma unroll
        for (int cc = 0; cc < 4; cc++){
            int c0 = cc*128 + lane*2;
            ull a[4][2], b[4][2];
            #pragma unroll
            for (int r = 0; r < 4; r++){
                a[r][0] = *(const ull*)&s_cap[(tt0+r)*CD + c0];
                a[r][1] = *(const ull*)&s_cap[(tt0+r)*CD + c0 + 64];
                b[r][0] = *(const ull*)&s_img[(ll0+r)*CD + c0];
                b[r][1] = *(const ull*)&s_img[(ll0+r)*CD + c0 + 64];
            }
            #pragma unroll
            for (int i = 0; i < 4; i++)
                #pragma unroll
                for (int j = 0; j < 4; j++){
                    fma2(acc[i*4+j], a[i][0], b[j][0]);
                    fma2(acc[i*4+j], a[i][1], b[j][1]);
                }
        }
        float r[16];
        #pragma unroll
        for (int q = 0; q < 16; q++){ float2 f = upk2(acc[q]); r[q] = warpSum(f.x + f.y); }
        if (lane == 0){
            #pragma unroll
            for (int i = 0; i < 4; i++)
                #pragma unroll
                for (int j = 0; j < 4; j++){
                    int t = tt0 + i, l = ll0 + j;
                    g_score[((size_t)t*BV + v)*LV + l0 + l] = s_self[l] + r[i*4+j]*s_inv[l];
                }
        }
    }
}

// ---------------- exact stable descending-rank + extra token ------------------
__global__ void k_rank(const float* __restrict__ img, float* __restrict__ out_mask){
    int pair = blockIdx.x; int v = pair % BV;
    __shared__ float s_sc[LV];
    __shared__ int   s_non[NNON];
    __shared__ float s_nw[NNON];
    __shared__ float s_max, s_sum;
    __shared__ float s_red[8];
    for (int l = threadIdx.x; l < LV; l += 256) s_sc[l] = g_score[(size_t)pair*LV + l];
    __syncthreads();
    for (int l = threadIdx.x; l < LV; l += 256){
        float sl = s_sc[l]; int r = 0;
        #pragma unroll 4
        for (int j = 0; j < LV; j++){
            float sj = s_sc[j];
            r += (int)((sj > sl) || ((sj == sl) && (j < l)));
        }
        out_mask[(size_t)pair*LV + l] = (r < NKEEP) ? 1.f : 0.f;
        if (r < NKEEP) g_keep[(size_t)pair*NKEEP + r] = l;
        else {
            s_non[r - NKEEP] = l;
            if (r == NKEEP) s_max = sl;
        }
    }
    __syncthreads();
    float local = 0.f;
    for (int j = threadIdx.x; j < NNON; j += 256){
        float e = expf(s_sc[s_non[j]] - s_max);
        s_nw[j] = e; local += e;
    }
    local = warpSum(local);
    if ((threadIdx.x & 31) == 0) s_red[threadIdx.x>>5] = local;
    __syncthreads();
    if (threadIdx.x == 0){ float S = 0.f; for (int i = 0; i < 8; i++) S += s_red[i]; s_sum = S; }
    __syncthreads();
    float invs = 1.f / s_sum;
    for (int c = threadIdx.x; c < CD; c += 256){
        float acc = 0.f;
        #pragma unroll 4
        for (int j = 0; j < NNON; j++) acc += s_nw[j] * img[((size_t)v*LV + s_non[j])*CD + c];
        g_extra[(size_t)pair*CD + c] = acc*invs;
    }
}

// ---------------- per-token LN -> W1 -> gelu -> W2 (w_pre) --------------------
#define TOKTILE 28
#define XN_P 30
__global__ void __launch_bounds__(256) k_wpre(
    const float* __restrict__ img, const float* __restrict__ gamma, const float* __restrict__ beta,
    const float* __restrict__ W1, const float* __restrict__ b1,
    const float* __restrict__ W2, const float* __restrict__ b2)
{
    extern __shared__ float sm[];
    float* s_xnT = sm;                 // CD*XN_P
    float* s_h   = sm + CD*XN_P;       // TOKTILE*HID
    int v = blockIdx.x, l0 = blockIdx.y*TOKTILE;
    int tid = threadIdx.x, warp = tid>>5, lane = tid & 31;

    for (int tt = warp; tt < TOKTILE; tt += 8){
        const float* x = img + ((size_t)v*LV + l0 + tt)*CD;
        float s = 0.f, s2 = 0.f;
        for (int c = lane; c < CD; c += 32){ float xv = x[c]; s += xv; s2 += xv*xv; }
        s = warpSum(s); s2 = warpSum(s2);
        float mu = s / (float)CD;
        float var = s2 / (float)CD - mu*mu;
        float rstd = rsqrtf(var + 1e-5f);
        for (int c = lane; c < CD; c += 32)
            s_xnT[c*XN_P + tt] = (x[c] - mu)*rstd*gamma[c] + beta[c];
    }
    __syncthreads();

    {
        int hc = tid & 127;
        int g  = tid >> 7;
        bool act = hc < HID;
        ull acc2[7] = {0ull,0ull,0ull,0ull,0ull,0ull,0ull};
        int tbase = g*14;
        for (int c = 0; c < CD; c++){
            float w1 = act ? W1[c*HID + hc] : 0.f;
            ull w2v = pk2(w1, w1);
            const ull* xr = (const ull*)&s_xnT[c*XN_P + tbase];
            #pragma unroll
            for (int j = 0; j < 7; j++) fma2(acc2[j], w2v, xr[j]);
        }
        if (act){
            float bb = b1[hc];
            #pragma unroll
            for (int j = 0; j < 7; j++){
                float2 hv = upk2(acc2[j]);
                float a0 = hv.x + bb, a1 = hv.y + bb;
                s_h[(tbase + 2*j    )*HID + hc] = 0.5f*a0*(1.f + erff(a0*0.70710678118654752440f));
                s_h[(tbase + 2*j + 1)*HID + hc] = 0.5f*a1*(1.f + erff(a1*0.70710678118654752440f));
            }
        }
    }
    __syncthreads();

    for (int idx = tid; idx < TOKTILE*KEEPED; idx += 256){
        int tt = idx / KEEPED, p = idx % KEEPED;
        float acc = b2[p];
        const float* hr = s_h + tt*HID;
        #pragma unroll 6
        for (int hh = 0; hh < HID; hh++) acc += hr[hh] * W2[hh*KEEPED + p];
        g_wpre[((size_t)v*LV + l0 + tt)*KEEPED + p] = acc;
    }
}

// ---------------- big per-(t,v) kernel ----------------------------------------
// smem layout (floats):
#define OFF_W    25600            // s_sel 50*512 before it
#define W_PITCH  100
#define W_ROWS   52
#define OFF_UN   30800            // union region, 25600 floats
#define OFF_KEEP 56400            // 104 ints
#define OFF_INV  56504            // 52
#define OFF_SIM  56556
#define SMEM_BIG_FLOATS 56560
// union sublayout (attention phase)
#define U_CAP   0                 // 24*512 = 12288
#define U_G     12288             // 50 rows pitch 53 = 2650
#define G_PITCH 53
#define U_SIMS  14944             // 24 rows pitch 52 = 1248
#define U_WS    16192             // 16*52 = 832

__global__ void __launch_bounds__(512,1) k_big(
    const float* __restrict__ img, const float* __restrict__ scale_ptr, float* __restrict__ out)
{
    extern __shared__ float sm[];
    float* s_sel  = sm;                     // 50*512
    float* s_w    = sm + OFF_W;             // 52 rows pitch 100
    float* s_un   = sm + OFF_UN;            // union
    int*   s_keep = (int*)(sm + OFF_KEEP);  // 100 (+pad)
    float* s_invp = sm + OFF_INV;
    float* s_sim  = sm + OFF_SIM;

    int tid = threadIdx.x, warp = tid>>5, lane = tid & 31;
    int pair = blockIdx.x, t = pair / BV, v = pair % BV;
    if (tid == 0) s_sim[0] = 0.f;
    for (int k = tid; k < 100; k += 512) s_keep[k] = (k < NKEEP) ? g_keep[(size_t)pair*NKEEP + k] : 0;
    __syncthreads();
    float scl = scale_ptr[0];

    // gather w_pre for kept tokens (pad rows/cols with 0)
    for (int idx = tid; idx < W_ROWS*W_PITCH; idx += 512){
        int p = idx / W_PITCH, k = idx % W_PITCH;
        s_w[idx] = (p < KEEPED && k < NKEEP)
                 ? g_wpre[((size_t)v*LV + s_keep[k])*KEEPED + p] * scl : 0.f;
    }
    __syncthreads();

    // softmax over k (k<98) per p row
    for (int p = warp; p < KEEPED; p += 16){
        float m = -1e30f;
        for (int k = lane; k < NKEEP; k += 32) m = fmaxf(m, s_w[p*W_PITCH + k]);
        m = warpMax(m);
        float s = 0.f;
        for (int k = lane; k < NKEEP; k += 32){
            float e = expf(s_w[p*W_PITCH + k] - m);
            s_w[p*W_PITCH + k] = e; s += e;
        }
        s = warpSum(s);
        float inv = 1.f / s;
        for (int k = lane; k < NKEEP; k += 32) s_w[p*W_PITCH + k] *= inv;
    }
    __syncthreads();

    // ---- aggr: 2 outer halves of C; stage 100 rows x 256 floats each ----
    {
        int hc = warp & 3;        // half-chunk (64 floats) within the 256
        int pg = warp >> 2;       // 0..3 -> p0 = pg*13
        int p0 = pg*13;
        for (int outer = 0; outer < 2; outer++){
            int c_base = outer*256;
            for (int idx = tid; idx < 100*256; idx += 512){
                int k = idx >> 8, cc = idx & 255;
                s_un[idx] = img[((size_t)v*LV + s_keep[k])*CD + c_base + cc];
            }
            __syncthreads();
            ull acc[13];
            #pragma unroll
            for (int j = 0; j < 13; j++) acc[j] = 0ull;
            int rbase = hc*64 + lane*2;
            for (int k4 = 0; k4 < 25; k4++){
                float4 wv[13];
                #pragma unroll
                for (int j = 0; j < 13; j++)
                    wv[j] = *(const float4*)&s_w[(p0+j)*W_PITCH + k4*4];
                #pragma unroll
                for (int kk = 0; kk < 4; kk++){
                    ull tv = *(const ull*)&s_un[(k4*4+kk)*256 + rbase];
                    #pragma unroll
                    for (int j = 0; j < 13; j++){
                        float w = (kk==0)?wv[j].x:(kk==1)?wv[j].y:(kk==2)?wv[j].z:wv[j].w;
                        fma2(acc[j], pk2(w, w), tv);
                    }
                }
            }
            #pragma unroll
            for (int j = 0; j < 13; j++){
                int p = p0 + j;
                if (p < KEEPED) *(ull*)&s_sel[p*CD + c_base + rbase] = acc[j];
            }
            __syncthreads();
        }
    }

    // extra token row + load normalized captions into union
    for (int c = tid; c < CD; c += 512) s_sel[49*CD + c] = g_extra[(size_t)pair*CD + c];
    for (int i = tid; i < NW*CD; i += 512) s_un[U_CAP + i] = g_cap_norm[((size_t)t*NW)*CD + i];
    __syncthreads();

    // ---- G (Gram, triangle of 13x13 4-tiles = 91) + sims (6x13 = 78) ----
    float* s_G    = s_un + U_G;
    float* s_sims = s_un + U_SIMS;
    float* s_ws   = s_un + U_WS;
    for (int tile = warp; tile < 169; tile += 16){
        const float* Abase; const float* Bbase;
        int ar0, br0, isG;
        if (tile < 91){
            int i = 0, rem = tile;
            while (rem >= 13 - i){ rem -= 13 - i; i++; }
            int j = i + rem;
            Abase = s_sel; Bbase = s_sel; ar0 = i*4; br0 = j*4; isG = 1;
        } else {
            int s = tile - 91;
            Abase = s_un + U_CAP; Bbase = s_sel;
            ar0 = (s / 13)*4; br0 = (s % 13)*4; isG = 0;
        }
        ull acc[16];
        #pragma unroll
        for (int q = 0; q < 16; q++) acc[q] = 0ull;
        #pragma unroll
        for (int cc = 0; cc < 4; cc++){
            int c0 = cc*128 + lane*2;
            ull a[4][2], b[4][2];
            #pragma unroll
            for (int r = 0; r < 4; r++){
                a[r][0] = *(const ull*)&Abase[(ar0+r)*CD + c0];
                a[r][1] = *(const ull*)&Abase[(ar0+r)*CD + c0 + 64];
                b[r][0] = *(const ull*)&Bbase[(br0+r)*CD + c0];
                b[r][1] = *(const ull*)&Bbase[(br0+r)*CD + c0 + 64];
            }
            #pragma unroll
            for (int i = 0; i < 4; i++)
                #pragma unroll
                for (int j = 0; j < 4; j++){
                    fma2(acc[i*4+j], a[i][0], b[j][0]);
                    fma2(acc[i*4+j], a[i][1], b[j][1]);
                }
        }
        float r[16];
        #pragma unroll
        for (int q = 0; q < 16; q++){ float2 f = upk2(acc[q]); r[q] = warpSum(f.x + f.y); }
        if (lane == 0){
            if (isG){
                #pragma unroll
                for (int i = 0; i < 4; i++)
                    #pragma unroll
                    for (int j = 0; j < 4; j++){
                        int p = ar0 + i, pp = br0 + j;
                        if (p < 50 && pp < 50){
                            s_G[p*G_PITCH + pp] = r[i*4+j];
                            s_G[pp*G_PITCH + p] = r[i*4+j];
                        }
                    }
            } else {
                #pragma unroll
                for (int i = 0; i < 4; i++)
                    #pragma unroll
                    for (int j = 0; j < 4; j++){
                        int w = ar0 + i, p = br0 + j;
                        if (w < NW && p < 50) s_sims[w*52 + p] = r[i*4+j];
                    }
            }
        }
    }
    __syncthreads();
    if (tid < 50) s_invp[tid] = 1.f / fmaxf(sqrtf(s_G[tid*G_PITCH + tid]), 1e-12f);
    __syncthreads();

    // ---- per-word: num = sum a_p s_p ; den = b^T G b, b = a*inv ----
    for (int w = warp; w < NW; w += 16){
        int p1 = lane, p2 = 32 + lane;
        bool v2 = (p2 < 50);
        float i1 = s_invp[p1], i2 = v2 ? s_invp[p2] : 0.f;
        float s1 = s_sims[w*52 + p1]*i1;
        float s2 = v2 ? s_sims[w*52 + p2]*i2 : -1e30f;
        float m = warpMax(fmaxf(s1, s2));
        float a1 = expf(4.f*(s1 - m));
        float a2 = v2 ? expf(4.f*(s2 - m)) : 0.f;
        float b1v = a1*i1, b2v = a2*i2;
        float* ws = s_ws + warp*52;
        ws[p1] = b1v;
        if (lane < 20) ws[p2] = v2 ? b2v : 0.f;
        __syncwarp();
        float num = warpSum(a1*s1 + (v2 ? a2*s2 : 0.f));
        float t1 = 0.f, t2 = 0.f;
        for (int pp = 0; pp < 50; pp++){
            float bb = ws[pp];
            t1 += bb * s_G[p1*G_PITCH + pp];
            if (v2) t2 += bb * s_G[p2*G_PITCH + pp];
        }
        float den = warpSum(b1v*t1 + (v2 ? b2v*t2 : 0.f));
        if (lane == 0){
            float wsim = num / fmaxf(sqrtf(den), 1e-12f);
            atomicAdd(s_sim, wsim);
        }
        __syncwarp();
    }
    __syncthreads();
    if (tid == 0) out[(size_t)v*BT + t] = s_sim[0] / (float)NW;
}

// -------------------------------- launcher ------------------------------------
extern "C" void kernel_launch(void* const* d_in, const int* in_sizes, int n_in,
                              void* d_out, int out_size)
{
    const float* img   = (const float*)d_in[0];
    const float* cap   = (const float*)d_in[1];
    const float* gamma = (const float*)d_in[3];
    const float* beta  = (const float*)d_in[4];
    const float* W1    = (const float*)d_in[5];
    const float* b1    = (const float*)d_in[6];
    const float* W2    = (const float*)d_in[7];
    const float* b2    = (const float*)d_in[8];
    const float* scale = (const float*)d_in[9];

    float* out_sims = (float*)d_out;               // [BV, BT]
    float* out_mask = (float*)d_out + BV*BT;       // [BT, BV, LV]

    const int SMEM_SCORE = (BT*CD + SC_LT*CD + 2*SC_LT)*4;
    const int SMEM_WPRE  = (CD*XN_P + TOKTILE*HID)*4;
    const int SMEM_BIG   = SMEM_BIG_FLOATS*4;

    cudaFuncSetAttribute(k_score, cudaFuncAttributeMaxDynamicSharedMemorySize, SMEM_SCORE);
    cudaFuncSetAttribute(k_wpre,  cudaFuncAttributeMaxDynamicSharedMemorySize, SMEM_WPRE);
    cudaFuncSetAttribute(k_big,   cudaFuncAttributeMaxDynamicSharedMemorySize, SMEM_BIG);

    k_glo<<<BV, 256>>>(img, LV, 0);
    k_glo<<<BT, 256>>>(cap, NW, 1);
    k_img_tok<<<BV*LV, 128>>>(img);
    k_cap_tok<<<BT*NW, 128>>>(cap);
    k_score<<<dim3(BV, 7), 256, SMEM_SCORE>>>(img);
    k_rank<<<PAIRS, 256>>>(img, out_mask);
    k_wpre<<<dim3(BV, 7), 256, SMEM_WPRE>>>(img, gamma, beta, W1, b1, W2, b2);
    k_big<<<PAIRS, 512, SMEM_BIG>>>(img, scale, out_sims);
}

// round 4
// speedup vs baseline: 1.7690x; 1.1306x over previous
#include <cuda_runtime.h>
#include <math.h>

#define BV 64
#define LV 196
#define BT 32
#define NW 24
#define CD 512
#define NKEEP 98
#define NNON 98
#define KEEPED 49
#define HID 102
#define PAIRS (BT*BV)
#define WP_PITCH 52

// ---------------- scratch (device globals; no allocation allowed) -------------
__device__ float g_img_inv[BV*LV];
__device__ float g_self[BV*LV];
__device__ float g_img_glo[BV*CD];
__device__ float g_cap_glo[BT*CD];
__device__ float g_cap_norm[BT*NW*CD];
__device__ float g_score[(size_t)PAIRS*LV];
__device__ int   g_keep[(size_t)PAIRS*NKEEP];
__device__ int   g_non[(size_t)PAIRS*NNON];
__device__ float g_nonw[(size_t)PAIRS*NNON];
__device__ float g_extra[(size_t)PAIRS*CD];
__device__ float g_wpre[(size_t)BV*LV*WP_PITCH];

typedef unsigned long long ull;

__device__ __forceinline__ float warpSum(float x){
    #pragma unroll
    for (int o=16;o;o>>=1) x += __shfl_xor_sync(0xffffffffu, x, o);
    return x;
}
__device__ __forceinline__ float warpMax(float x){
    #pragma unroll
    for (int o=16;o;o>>=1) x = fmaxf(x, __shfl_xor_sync(0xffffffffu, x, o));
    return x;
}

// packed f32x2 helpers (sm_103a FFMA2 path — PTX-only)
__device__ __forceinline__ ull pk2(float a, float b){
    ull r; asm("mov.b64 %0, {%1, %2};" : "=l"(r) : "f"(a), "f"(b)); return r;
}
__device__ __forceinline__ float2 upk2(ull v){
    float2 r; asm("mov.b64 {%0, %1}, %2;" : "=f"(r.x), "=f"(r.y) : "l"(v)); return r;
}
__device__ __forceinline__ void fma2(ull &d, ull a, ull b){
    asm("fma.rn.f32x2 %0, %1, %2, %0;" : "+l"(d) : "l"(a), "l"(b));
}

// ---------------- global token means, l2-normalized ---------------------------
__global__ void k_glo(const float* __restrict__ src, int L, int which){
    int b = blockIdx.x;
    __shared__ float s_mean[CD];
    __shared__ float s_red[32];
    for (int c = threadIdx.x; c < CD; c += blockDim.x){
        float s = 0.f;
        for (int l = 0; l < L; l++) s += src[((size_t)b*L + l)*CD + c];
        s_mean[c] = s / (float)L;
    }
    __syncthreads();
    float ss = 0.f;
    for (int c = threadIdx.x; c < CD; c += blockDim.x){ float x = s_mean[c]; ss += x*x; }
    ss = warpSum(ss);
    if ((threadIdx.x & 31) == 0) s_red[threadIdx.x>>5] = ss;
    __syncthreads();
    if (threadIdx.x < 32){
        float v = (threadIdx.x < (blockDim.x>>5)) ? s_red[threadIdx.x] : 0.f;
        v = warpSum(v);
        if (threadIdx.x == 0) s_red[0] = 1.f / fmaxf(sqrtf(v), 1e-12f);
    }
    __syncthreads();
    float inv = s_red[0];
    float* out = which ? g_cap_glo : g_img_glo;
    for (int c = threadIdx.x; c < CD; c += blockDim.x) out[(size_t)b*CD + c] = s_mean[c]*inv;
}

// ---------------- per-img-token inv-norm + self_attn -------------------------
__global__ void k_img_tok(const float* __restrict__ img){
    int idx = blockIdx.x;
    int v = idx / LV;
    const float* x   = img + (size_t)idx*CD;
    const float* glo = g_img_glo + (size_t)v*CD;
    float ss = 0.f, dg = 0.f;
    for (int c = threadIdx.x; c < CD; c += 128){ float t = x[c]; ss += t*t; dg += t*glo[c]; }
    ss = warpSum(ss); dg = warpSum(dg);
    __shared__ float r1[4], r2[4];
    if ((threadIdx.x & 31) == 0){ r1[threadIdx.x>>5] = ss; r2[threadIdx.x>>5] = dg; }
    __syncthreads();
    if (threadIdx.x == 0){
        float S = r1[0]+r1[1]+r1[2]+r1[3];
        float D = r2[0]+r2[1]+r2[2]+r2[3];
        float inv = 1.f / fmaxf(sqrtf(S), 1e-12f);
        g_img_inv[idx] = inv;
        g_self[idx]    = D*inv;
    }
}

// ---------------- normalized caption tokens -----------------------------------
__global__ void k_cap_tok(const float* __restrict__ cap){
    int idx = blockIdx.x;
    const float* x = cap + (size_t)idx*CD;
    float ss = 0.f;
    for (int c = threadIdx.x; c < CD; c += 128){ float t = x[c]; ss += t*t; }
    ss = warpSum(ss);
    __shared__ float r[4]; __shared__ float s_inv;
    if ((threadIdx.x & 31) == 0) r[threadIdx.x>>5] = ss;
    __syncthreads();
    if (threadIdx.x == 0) s_inv = 1.f / fmaxf(sqrtf(r[0]+r[1]+r[2]+r[3]), 1e-12f);
    __syncthreads();
    float inv = s_inv;
    for (int c = threadIdx.x; c < CD; c += 128) g_cap_norm[(size_t)idx*CD + c] = x[c]*inv;
}

// ---------------- score via 4x4 register-tiled dots ---------------------------
#define SC_LT 28
__global__ void __launch_bounds__(256) k_score(const float* __restrict__ img){
    extern __shared__ float sm[];
    float* s_cap = sm;                   // 32*512
    float* s_img = sm + BT*CD;           // 28*512
    float* s_self = sm + BT*CD + SC_LT*CD;
    float* s_inv  = s_self + SC_LT;
    int v = blockIdx.x, l0 = blockIdx.y*SC_LT;
    int tid = threadIdx.x, warp = tid>>5, lane = tid & 31;
    for (int i = tid; i < BT*CD; i += 256) s_cap[i] = g_cap_glo[i];
    for (int i = tid; i < SC_LT*CD; i += 256) s_img[i] = img[((size_t)v*LV + l0)*CD + i];
    if (tid < SC_LT){ s_self[tid] = g_self[v*LV + l0 + tid]; s_inv[tid] = g_img_inv[v*LV + l0 + tid]; }
    __syncthreads();
    for (int tile = warp; tile < 56; tile += 8){
        int tt0 = (tile / 7)*4, ll0 = (tile % 7)*4;
        ull acc[16];
        #pragma unroll
        for (int q = 0; q < 16; q++) acc[q] = 0ull;
        #pragma unroll
        for (int cc = 0; cc < 4; cc++){
            int c0 = cc*128 + lane*4;
            ulonglong2 a[4], b[4];
            #pragma unroll
            for (int r = 0; r < 4; r++){
                a[r] = *(const ulonglong2*)&s_cap[(tt0+r)*CD + c0];
                b[r] = *(const ulonglong2*)&s_img[(ll0+r)*CD + c0];
            }
            #pragma unroll
            for (int i = 0; i < 4; i++)
                #pragma unroll
                for (int j = 0; j < 4; j++){
                    fma2(acc[i*4+j], a[i].x, b[j].x);
                    fma2(acc[i*4+j], a[i].y, b[j].y);
                }
        }
        float r[16];
        #pragma unroll
        for (int q = 0; q < 16; q++){ float2 f = upk2(acc[q]); r[q] = warpSum(f.x + f.y); }
        if (lane == 0){
            #pragma unroll
            for (int i = 0; i < 4; i++)
                #pragma unroll
                for (int j = 0; j < 4; j++){
                    int t = tt0 + i, l = ll0 + j;
                    g_score[((size_t)t*BV + v)*LV + l0 + l] = s_self[l] + r[i*4+j]*s_inv[l];
                }
        }
    }
}

// ---------------- exact stable rank + mask + softmax weights ------------------
__global__ void k_rank(float* __restrict__ out_mask){
    int pair = blockIdx.x;
    __shared__ float s_sc[LV];
    __shared__ int   s_non[NNON];
    __shared__ float s_nw[NNON];
    __shared__ float s_max, s_sum;
    __shared__ float s_red[8];
    for (int l = threadIdx.x; l < LV; l += 256) s_sc[l] = g_score[(size_t)pair*LV + l];
    __syncthreads();
    for (int l = threadIdx.x; l < LV; l += 256){
        float sl = s_sc[l]; int r = 0;
        #pragma unroll 4
        for (int j = 0; j < LV; j++){
            float sj = s_sc[j];
            r += (int)((sj > sl) || ((sj == sl) && (j < l)));
        }
        out_mask[(size_t)pair*LV + l] = (r < NKEEP) ? 1.f : 0.f;
        if (r < NKEEP) g_keep[(size_t)pair*NKEEP + r] = l;
        else {
            s_non[r - NKEEP] = l;
            if (r == NKEEP) s_max = sl;
        }
    }
    __syncthreads();
    float local = 0.f;
    for (int j = threadIdx.x; j < NNON; j += 256){
        float e = expf(s_sc[s_non[j]] - s_max);
        s_nw[j] = e; local += e;
    }
    local = warpSum(local);
    if ((threadIdx.x & 31) == 0) s_red[threadIdx.x>>5] = local;
    __syncthreads();
    if (threadIdx.x == 0){ float S = 0.f; for (int i = 0; i < 8; i++) S += s_red[i]; s_sum = S; }
    __syncthreads();
    float invs = 1.f / s_sum;
    for (int j = threadIdx.x; j < NNON; j += 256){
        g_non [(size_t)pair*NNON + j] = s_non[j];
        g_nonw[(size_t)pair*NNON + j] = s_nw[j]*invs;
    }
}

// ---------------- extra token: per-(v, c-chunk), img staged once --------------
// grid (BV, 4), 512 threads. smem: X 196x128, nwp(ull) 32x98, non 32x98
#define EX_X    0
#define EX_NWP  25088            // ull region: 3136 ull = 6272 floats
#define EX_NON  31360            // 3136 ints
#define EX_FLOATS 34496
__global__ void __launch_bounds__(512) k_extra(const float* __restrict__ img){
    extern __shared__ float sm[];
    float* s_X   = sm + EX_X;
    ull*   s_nwp = (ull*)(sm + EX_NWP);
    int*   s_non = (int*)(sm + EX_NON);
    int v = blockIdx.x, c0 = blockIdx.y*128;
    int tid = threadIdx.x;
    for (int idx = tid; idx < LV*32; idx += 512){
        int row = idx >> 5, f = idx & 31;
        *(float4*)&s_X[row*128 + f*4] = *(const float4*)&img[((size_t)v*LV + row)*CD + c0 + f*4];
    }
    for (int i = tid; i < BT*NNON; i += 512){
        int t = i / NNON, j = i % NNON;
        size_t pair = (size_t)t*BV + v;
        float w = g_nonw[pair*NNON + j];
        s_nwp[t*NNON + j] = pk2(w, w);
        s_non[t*NNON + j] = g_non[pair*NNON + j];
    }
    __syncthreads();
    int cp = tid & 63, tg = tid >> 6;   // 64 c-pairs, 8 t-groups
    for (int t = tg; t < BT; t += 8){
        ull acc = 0ull;
        for (int j = 0; j < NNON; j++){
            int l = s_non[t*NNON + j];
            fma2(acc, s_nwp[t*NNON + j], *(const ull*)&s_X[l*128 + cp*2]);
        }
        *(ull*)&g_extra[((size_t)t*BV + v)*CD + c0 + cp*2] = acc;
    }
}

// ---------------- per-token LN -> W1 -> gelu -> W2 (w_pre, pitch 52) ----------
#define TOKTILE 28
#define XN_P 30
__global__ void __launch_bounds__(256) k_wpre(
    const float* __restrict__ img, const float* __restrict__ gamma, const float* __restrict__ beta,
    const float* __restrict__ W1, const float* __restrict__ b1,
    const float* __restrict__ W2, const float* __restrict__ b2)
{
    extern __shared__ float sm[];
    float* s_xnT = sm;                 // CD*XN_P
    float* s_h   = sm + CD*XN_P;       // TOKTILE*HID
    int v = blockIdx.x, l0 = blockIdx.y*TOKTILE;
    int tid = threadIdx.x, warp = tid>>5, lane = tid & 31;

    for (int tt = warp; tt < TOKTILE; tt += 8){
        const float* x = img + ((size_t)v*LV + l0 + tt)*CD;
        float s = 0.f, s2 = 0.f;
        for (int c = lane; c < CD; c += 32){ float xv = x[c]; s += xv; s2 += xv*xv; }
        s = warpSum(s); s2 = warpSum(s2);
        float mu = s / (float)CD;
        float var = s2 / (float)CD - mu*mu;
        float rstd = rsqrtf(var + 1e-5f);
        for (int c = lane; c < CD; c += 32)
            s_xnT[c*XN_P + tt] = (x[c] - mu)*rstd*gamma[c] + beta[c];
    }
    __syncthreads();

    {
        int hc = tid & 127;
        int g  = tid >> 7;
        bool act = hc < HID;
        ull acc2[7] = {0ull,0ull,0ull,0ull,0ull,0ull,0ull};
        int tbase = g*14;
        for (int c = 0; c < CD; c++){
            float w1 = act ? W1[c*HID + hc] : 0.f;
            ull w2v = pk2(w1, w1);
            const ull* xr = (const ull*)&s_xnT[c*XN_P + tbase];
            #pragma unroll
            for (int j = 0; j < 7; j++) fma2(acc2[j], w2v, xr[j]);
        }
        if (act){
            float bb = b1[hc];
            #pragma unroll
            for (int j = 0; j < 7; j++){
                float2 hv = upk2(acc2[j]);
                float a0 = hv.x + bb, a1 = hv.y + bb;
                s_h[(tbase + 2*j    )*HID + hc] = 0.5f*a0*(1.f + erff(a0*0.70710678118654752440f));
                s_h[(tbase + 2*j + 1)*HID + hc] = 0.5f*a1*(1.f + erff(a1*0.70710678118654752440f));
            }
        }
    }
    __syncthreads();

    for (int idx = tid; idx < TOKTILE*KEEPED; idx += 256){
        int tt = idx / KEEPED, p = idx % KEEPED;
        float acc = b2[p];
        const float* hr = s_h + tt*HID;
        #pragma unroll 6
        for (int hh = 0; hh < HID; hh++) acc += hr[hh] * W2[hh*KEEPED + p];
        g_wpre[((size_t)v*LV + l0 + tt)*WP_PITCH + p] = acc;
    }
}

// ---------------- big per-(t,v) kernel ----------------------------------------
// smem (floats):
//  s_sel  [0, 25600)          50x512
//  s_wpd  [25600, 36800)      56x100 ull (dup-packed weights)
//  union  [36800, 53824)      aggr staging 50x256 | {cap 24x512, G, sims, ws}
//  keep   [53824, 53928)      104 ints
//  invp   [53928, 53980)
//  sim    [53980]
#define OFF_WPD  25600
#define OFF_UN   36800
#define U_G      12288
#define G_PITCH  53
#define U_SIMS   14944
#define U_WS     16192
#define OFF_KEEP 53824
#define OFF_INV  53928
#define OFF_SIM  53980
#define SMEM_BIG_FLOATS 53984

__global__ void __launch_bounds__(512,1) k_big(
    const float* __restrict__ img, const float* __restrict__ scale_ptr, float* __restrict__ out)
{
    extern __shared__ float sm[];
    float* s_sel  = sm;
    ull*   s_wpd  = (ull*)(sm + OFF_WPD);
    float* s_un   = sm + OFF_UN;
    int*   s_keep = (int*)(sm + OFF_KEEP);
    float* s_invp = sm + OFF_INV;
    float* s_sim  = sm + OFF_SIM;

    int tid = threadIdx.x, warp = tid>>5, lane = tid & 31;
    int pair = blockIdx.x, t = pair / BV, v = pair % BV;
    if (tid == 0) s_sim[0] = 0.f;
    for (int k = tid; k < 100; k += 512) s_keep[k] = (k < NKEEP) ? g_keep[(size_t)pair*NKEEP + k] : 0;
    __syncthreads();
    float scl = scale_ptr[0];

    // gather w_pre (float) into union: s_wf[p][k], pitch 100
    float* s_wf = s_un;
    for (int idx = tid; idx < 100*13; idx += 512){
        int k = idx / 13, q = idx % 13;
        const float* row = g_wpre + (size_t)(v*LV + s_keep[k])*WP_PITCH;
        float4 w4 = *(const float4*)&row[q*4];
        s_wf[(q*4+0)*100 + k] = w4.x*scl;
        s_wf[(q*4+1)*100 + k] = w4.y*scl;
        s_wf[(q*4+2)*100 + k] = w4.z*scl;
        s_wf[(q*4+3)*100 + k] = w4.w*scl;
    }
    __syncthreads();

    // softmax over k per p row
    for (int p = warp; p < KEEPED; p += 16){
        float m = -1e30f;
        for (int k = lane; k < NKEEP; k += 32) m = fmaxf(m, s_wf[p*100 + k]);
        m = warpMax(m);
        float s = 0.f;
        for (int k = lane; k < NKEEP; k += 32){
            float e = expf(s_wf[p*100 + k] - m);
            s_wf[p*100 + k] = e; s += e;
        }
        s = warpSum(s);
        float inv = 1.f / s;
        for (int k = lane; k < NKEEP; k += 32) s_wf[p*100 + k] *= inv;
    }
    __syncthreads();

    // pack duplicated weights: s_wpd[p][k] (56x100), zero pad
    for (int idx = tid; idx < 56*100; idx += 512){
        int p = idx / 100, k = idx % 100;
        float w = (p < KEEPED && k < NKEEP) ? s_wf[p*100 + k] : 0.f;
        s_wpd[idx] = pk2(w, w);
    }
    // (sync happens at top of the staging loop below)

    // ---- aggr: c-halves x k-halves; warp = (p-grp of 7) x (c-grp of 128) ----
    {
        int pg = warp >> 1, cgrp = warp & 1;
        int p0 = pg*7;
        int cbase = cgrp*128 + lane*4;       // within the 256-c half
        for (int ch = 0; ch < 2; ch++){
            ull accA[7], accB[7];
            #pragma unroll
            for (int j = 0; j < 7; j++){ accA[j] = 0ull; accB[j] = 0ull; }
            for (int kh = 0; kh < 2; kh++){
                __syncthreads();
                for (int idx = tid; idx < 50*64; idx += 512){
                    int row = idx >> 6, f = idx & 63;
                    *(float4*)&s_un[row*256 + f*4] =
                        *(const float4*)&img[((size_t)v*LV + s_keep[kh*50 + row])*CD + ch*256 + f*4];
                }
                __syncthreads();
                int kw0 = kh*50;
                #pragma unroll 5
                for (int k2 = 0; k2 < 25; k2++){
                    ulonglong2 x0 = *(const ulonglong2*)&s_un[(2*k2  )*256 + cbase];
                    ulonglong2 x1 = *(const ulonglong2*)&s_un[(2*k2+1)*256 + cbase];
                    #pragma unroll
                    for (int j = 0; j < 7; j++){
                        ulonglong2 wv = *(const ulonglong2*)&s_wpd[(p0+j)*100 + kw0 + 2*k2];
                        fma2(accA[j], wv.x, x0.x);
                        fma2(accB[j], wv.x, x0.y);
                        fma2(accA[j], wv.y, x1.x);
                        fma2(accB[j], wv.y, x1.y);
                    }
                }
            }
            #pragma unroll
            for (int j = 0; j < 7; j++){
                int p = p0 + j;
                if (p < KEEPED)
                    *(ulonglong2*)&s_sel[p*CD + ch*256 + cbase] = make_ulonglong2(accA[j], accB[j]);
            }
        }
    }
    __syncthreads();

    // extra token row + captions into union
    for (int c = tid; c < CD; c += 512) s_sel[49*CD + c] = g_extra[(size_t)pair*CD + c];
    for (int i = tid; i < NW*CD; i += 512) s_un[i] = g_cap_norm[((size_t)t*NW)*CD + i];
    __syncthreads();

    // ---- G (triangle of 13x13 4-tiles = 91) + sims (6x13 = 78) ----
    float* s_G    = s_un + U_G;
    float* s_sims = s_un + U_SIMS;
    float* s_ws   = s_un + U_WS;
    for (int tile = warp; tile < 169; tile += 16){
        const float* Abase; const float* Bbase;
        int ar0, br0, isG;
        if (tile < 91){
            int i = 0, rem = tile;
            while (rem >= 13 - i){ rem -= 13 - i; i++; }
            int j = i + rem;
            Abase = s_sel; Bbase = s_sel; ar0 = i*4; br0 = j*4; isG = 1;
        } else {
            int s = tile - 91;
            Abase = s_un; Bbase = s_sel;
            ar0 = (s / 13)*4; br0 = (s % 13)*4; isG = 0;
        }
        ull acc[16];
        #pragma unroll
        for (int q = 0; q < 16; q++) acc[q] = 0ull;
        #pragma unroll
        for (int cc = 0; cc < 4; cc++){
            int c0 = cc*128 + lane*4;
            ulonglong2 a[4], b[4];
            #pragma unroll
            for (int r = 0; r < 4; r++){
                a[r] = *(const ulonglong2*)&Abase[(ar0+r)*CD + c0];
                b[r] = *(const ulonglong2*)&Bbase[(br0+r)*CD + c0];
            }
            #pragma unroll
            for (int i = 0; i < 4; i++)
                #pragma unroll
                for (int j = 0; j < 4; j++){
                    fma2(acc[i*4+j], a[i].x, b[j].x);
                    fma2(acc[i*4+j], a[i].y, b[j].y);
                }
        }
        float r[16];
        #pragma unroll
        for (int q = 0; q < 16; q++){ float2 f = upk2(acc[q]); r[q] = warpSum(f.x + f.y); }
        if (lane == 0){
            if (isG){
                #pragma unroll
                for (int i = 0; i < 4; i++)
                    #pragma unroll
                    for (int j = 0; j < 4; j++){
                        int p = ar0 + i, pp = br0 + j;
                        if (p < 50 && pp < 50){
                            s_G[p*G_PITCH + pp] = r[i*4+j];
                            s_G[pp*G_PITCH + p] = r[i*4+j];
                        }
                    }
            } else {
                #pragma unroll
                for (int i = 0; i < 4; i++)
                    #pragma unroll
                    for (int j = 0; j < 4; j++){
                        int w = ar0 + i, p = br0 + j;
                        if (w < NW && p < 50) s_sims[w*52 + p] = r[i*4+j];
                    }
            }
        }
    }
    __syncthreads();
    if (tid < 50) s_invp[tid] = 1.f / fmaxf(sqrtf(s_G[tid*G_PITCH + tid]), 1e-12f);
    __syncthreads();

    // ---- per-word: num = sum a_p s_p ; den = b^T G b, b = a*inv ----
    for (int w = warp; w < NW; w += 16){
        int p1 = lane, p2 = 32 + lane;
        bool v2 = (p2 < 50);
        float i1 = s_invp[p1], i2 = v2 ? s_invp[p2] : 0.f;
        float s1 = s_sims[w*52 + p1]*i1;
        float s2 = v2 ? s_sims[w*52 + p2]*i2 : -1e30f;
        float m = warpMax(fmaxf(s1, s2));
        float a1 = expf(4.f*(s1 - m));
        float a2 = v2 ? expf(4.f*(s2 - m)) : 0.f;
        float b1v = a1*i1, b2v = a2*i2;
        float* ws = s_ws + warp*52;
        ws[p1] = b1v;
        if (lane < 20) ws[p2] = v2 ? b2v : 0.f;
        __syncwarp();
        float num = warpSum(a1*s1 + (v2 ? a2*s2 : 0.f));
        float t1 = 0.f, t2 = 0.f;
        for (int pp = 0; pp < 50; pp++){
            float bb = ws[pp];
            t1 += bb * s_G[p1*G_PITCH + pp];
            if (v2) t2 += bb * s_G[p2*G_PITCH + pp];
        }
        float den = warpSum(b1v*t1 + (v2 ? b2v*t2 : 0.f));
        if (lane == 0){
            float wsim = num / fmaxf(sqrtf(den), 1e-12f);
            atomicAdd(s_sim, wsim);
        }
        __syncwarp();
    }
    __syncthreads();
    if (tid == 0) out[(size_t)v*BT + t] = s_sim[0] / (float)NW;
}

// -------------------------------- launcher ------------------------------------
extern "C" void kernel_launch(void* const* d_in, const int* in_sizes, int n_in,
                              void* d_out, int out_size)
{
    const float* img   = (const float*)d_in[0];
    const float* cap   = (const float*)d_in[1];
    const float* gamma = (const float*)d_in[3];
    const float* beta  = (const float*)d_in[4];
    const float* W1    = (const float*)d_in[5];
    const float* b1    = (const float*)d_in[6];
    const float* W2    = (const float*)d_in[7];
    const float* b2    = (const float*)d_in[8];
    const float* scale = (const float*)d_in[9];

    float* out_sims = (float*)d_out;               // [BV, BT]
    float* out_mask = (float*)d_out + BV*BT;       // [BT, BV, LV]

    const int SMEM_SCORE = (BT*CD + SC_LT*CD + 2*SC_LT)*4;
    const int SMEM_WPRE  = (CD*XN_P + TOKTILE*HID)*4;
    const int SMEM_BIG   = SMEM_BIG_FLOATS*4;
    const int SMEM_EX    = EX_FLOATS*4;

    cudaFuncSetAttribute(k_score, cudaFuncAttributeMaxDynamicSharedMemorySize, SMEM_SCORE);
    cudaFuncSetAttribute(k_wpre,  cudaFuncAttributeMaxDynamicSharedMemorySize, SMEM_WPRE);
    cudaFuncSetAttribute(k_big,   cudaFuncAttributeMaxDynamicSharedMemorySize, SMEM_BIG);
    cudaFuncSetAttribute(k_extra, cudaFuncAttributeMaxDynamicSharedMemorySize, SMEM_EX);

    k_glo<<<BV, 256>>>(img, LV, 0);
    k_glo<<<BT, 256>>>(cap, NW, 1);
    k_img_tok<<<BV*LV, 128>>>(img);
    k_cap_tok<<<BT*NW, 128>>>(cap);
    k_score<<<dim3(BV, 7), 256, SMEM_SCORE>>>(img);
    k_rank<<<PAIRS, 256>>>(out_mask);
    k_extra<<<dim3(BV, 4), 512, SMEM_EX>>>(img);
    k_wpre<<<dim3(BV, 7), 256, SMEM_WPRE>>>(img, gamma, beta, W1, b1, W2, b2);
    k_big<<<PAIRS, 512, SMEM_BIG>>>(img, scale, out_sims);
}